// round 15
// baseline (speedup 1.0000x reference)
#include <cuda_runtime.h>
#include <cuda_fp16.h>
#include <cstdint>
#include <math.h>

#define CN 512
#define NN 4096
#define HEADS 16
#define HD 32

// log2(e)/sqrt(32): folded into W'q / b'q so softmax uses ex2
#define QSCALE_LOG2E 0.2550348640f

// ---------------- scratch ----------------
__device__ uint32_t g_xt [NN * (CN / 2)];      // x fp16 c-pair packed, token-major
__device__ uint32_t g_wh [4 * CN * (CN / 2)];  // W' fp16 c-pair packed (q,k,v,o)
__device__ float    g_bp [4 * CN];             // folded biases
__device__ uint32_t g_qp [NN * (CN / 2)];      // Q fp16 d-pair packed, token-major
__device__ uint32_t g_kp [NN * (CN / 2)];      // K fp16 d-pair packed, token-major
__device__ uint32_t g_vp [CN * (NN / 2)];      // V fp16 key-pair packed [c][n/2]
__device__ uint32_t g_aot[NN * (CN / 2)];      // attn out fp16 c-pair packed, token-major
__device__ float2   g_cst[CN];                 // per-channel (sum, sumsq) of x
__device__ float4   g_coef[CN];                // (A1,B1, A21,B21)

// ================= helpers =================
__device__ __forceinline__ uint32_t smem_u32(const void* p){
    uint32_t a;
    asm("{ .reg .u64 t; cvta.to.shared.u64 t, %1; cvt.u32.u64 %0, t; }" : "=r"(a) : "l"(p));
    return a;
}
#define CP_ASYNC16(dst, src) \
    asm volatile("cp.async.cg.shared.global [%0], [%1], 16;" :: "r"(dst), "l"(src) : "memory")
#define CP_COMMIT() asm volatile("cp.async.commit_group;" ::: "memory")
#define CP_WAIT(n)  asm volatile("cp.async.wait_group %0;" :: "n"(n) : "memory")

__device__ __forceinline__ uint32_t pack_f16(float lo, float hi){
    uint32_t d;
    asm("cvt.rn.f16x2.f32 %0, %1, %2;" : "=r"(d) : "f"(hi), "f"(lo));
    return d;
}
__device__ __forceinline__ uint32_t ex2_f16x2(uint32_t x){
    uint32_t y;
    asm("ex2.approx.f16x2 %0, %1;" : "=r"(y) : "r"(x));
    return y;
}
__device__ __forceinline__ uint32_t hadd2(uint32_t a, uint32_t b){
    uint32_t y;
    asm("add.f16x2 %0, %1, %2;" : "=r"(y) : "r"(a), "r"(b));
    return y;
}
__device__ __forceinline__ void mma_f16(float c[4], const uint32_t a[4], uint32_t b0, uint32_t b1){
    asm volatile("mma.sync.aligned.m16n8k16.row.col.f32.f16.f16.f32 "
        "{%0,%1,%2,%3}, {%4,%5,%6,%7}, {%8,%9}, {%0,%1,%2,%3};"
        : "+f"(c[0]), "+f"(c[1]), "+f"(c[2]), "+f"(c[3])
        : "r"(a[0]), "r"(a[1]), "r"(a[2]), "r"(a[3]), "r"(b0), "r"(b1));
}
__device__ __forceinline__ void ldsm_x4(uint32_t& a, uint32_t& b, uint32_t& c, uint32_t& d,
                                        uint32_t addr){
    asm volatile("ldmatrix.sync.aligned.m8n8.x4.shared.b16 {%0,%1,%2,%3}, [%4];"
        : "=r"(a), "=r"(b), "=r"(c), "=r"(d) : "r"(addr));
}

// ---------------- double-GN coefficients (R10-verified) ----------------
__global__ __launch_bounds__(256) void gn_stats_ch(const float* __restrict__ in,
                                                   float2* __restrict__ cst)
{
    const int c = blockIdx.x;
    const float4* in4 = (const float4*)(in + (size_t)c * NN);
    float s = 0.f, q = 0.f;
    #pragma unroll
    for (int r = 0; r < 4; r++) {
        float4 t = in4[threadIdx.x + r * 256];
        s += t.x + t.y + t.z + t.w;
        q += t.x * t.x + t.y * t.y + t.z * t.z + t.w * t.w;
    }
    __shared__ float rs[8], rq[8];
    #pragma unroll
    for (int o = 16; o >= 1; o >>= 1) {
        s += __shfl_xor_sync(0xffffffffu, s, o);
        q += __shfl_xor_sync(0xffffffffu, q, o);
    }
    int lane = threadIdx.x & 31, wid = threadIdx.x >> 5;
    if (lane == 0) { rs[wid] = s; rq[wid] = q; }
    __syncthreads();
    if (wid == 0) {
        s = (lane < 8) ? rs[lane] : 0.f;
        q = (lane < 8) ? rq[lane] : 0.f;
        #pragma unroll
        for (int o = 4; o >= 1; o >>= 1) {
            s += __shfl_xor_sync(0xffffffffu, s, o);
            q += __shfl_xor_sync(0xffffffffu, q, o);
        }
        if (lane == 0) cst[c] = make_float2(s, q);
    }
}

__global__ __launch_bounds__(512) void gn_coef(
    const float2* __restrict__ cst, const float* __restrict__ w,
    const float* __restrict__ b, float4* __restrict__ coef)
{
    const int c = threadIdx.x;
    float2 p = cst[c];
    float s = p.x, q = p.y;
    #pragma unroll
    for (int o = 8; o >= 1; o >>= 1) {
        s += __shfl_xor_sync(0xffffffffu, s, o);
        q += __shfl_xor_sync(0xffffffffu, q, o);
    }
    const float inv_n = 1.f / 65536.f;
    float m1 = s * inv_n;
    float i1 = rsqrtf(q * inv_n - m1 * m1 + 1e-6f);
    float A1 = w[c] * i1, B1 = b[c] - m1 * A1;
    float mu = p.x * (1.f / 4096.f), e2 = p.y * (1.f / 4096.f);
    float mq = A1 * mu + B1;
    float eq = A1 * A1 * e2 + 2.f * A1 * B1 * mu + B1 * B1;
    float s2 = mq, q2 = eq;
    #pragma unroll
    for (int o = 8; o >= 1; o >>= 1) {
        s2 += __shfl_xor_sync(0xffffffffu, s2, o);
        q2 += __shfl_xor_sync(0xffffffffu, q2, o);
    }
    float m2 = s2 * (1.f / 16.f);
    float i2 = rsqrtf(q2 * (1.f / 16.f) - m2 * m2 + 1e-6f);
    float A2 = w[c] * i2, B2 = b[c] - m2 * A2;
    coef[c] = make_float4(A1, B1, A2 * A1, A2 * B1 + B2);
}

// ---------------- x -> fp16 token-major c-pair packed (staged transpose) -------
__global__ __launch_bounds__(256) void pack_xt(const float* __restrict__ x,
                                               uint32_t* __restrict__ xt)
{
    __shared__ uint32_t ts[8][132];
    const int t = threadIdx.x;
    const int n0 = blockIdx.x * 128, cbase = blockIdx.y * 16;
    const int p = t >> 5, l = t & 31;
    const int c0 = cbase + 2 * p;
    float4 a = *(const float4*)&x[(size_t)c0 * NN + n0 + 4 * l];
    float4 b = *(const float4*)&x[(size_t)(c0 + 1) * NN + n0 + 4 * l];
    uint4 u;
    u.x = pack_f16(a.x, b.x); u.y = pack_f16(a.y, b.y);
    u.z = pack_f16(a.z, b.z); u.w = pack_f16(a.w, b.w);
    *(uint4*)&ts[p][4 * l] = u;
    __syncthreads();
    const int tok = t >> 1, hf = t & 1;
    uint4 v;
    v.x = ts[hf * 4 + 0][tok]; v.y = ts[hf * 4 + 1][tok];
    v.z = ts[hf * 4 + 2][tok]; v.w = ts[hf * 4 + 3][tok];
    *(uint4*)&xt[(size_t)(n0 + tok) * (CN / 2) + (cbase >> 1) + hf * 4] = v;
}

// ---------------- fold GN into weights: warp-per-row rewrite (R14) -------------
// grid 256 x 256 thr; warp handles one (z,o) row: coalesced float2 W reads,
// fp16 pack writes, warp-shuffle bias reduction. No __syncthreads.
__global__ __launch_bounds__(256) void pack_w(
    const float* __restrict__ wq_, const float* __restrict__ wk_,
    const float* __restrict__ wv_, const float* __restrict__ wo_,
    const float* __restrict__ bq_, const float* __restrict__ bk_,
    const float* __restrict__ bv_, const float* __restrict__ bo_,
    const float4* __restrict__ coef,
    uint32_t* __restrict__ wh, float* __restrict__ bp)
{
    const int tid = threadIdx.x, lane = tid & 31, warp = tid >> 5;
    const int rg = blockIdx.x * 8 + warp;          // 0..2047
    const int z = rg >> 9, o = rg & 511;
    const float* W = (z == 0) ? wq_ : (z == 1) ? wk_ : (z == 2) ? wv_ : wo_;
    const float* B = (z == 0) ? bq_ : (z == 1) ? bk_ : (z == 2) ? bv_ : bo_;
    const float outsc = (z == 0) ? QSCALE_LOG2E : 1.f;

    float part = 0.f;
    #pragma unroll
    for (int j = 0; j < 8; j++) {
        int pr = lane + 32 * j;                    // c-pair index 0..255
        float2 w2 = *(const float2*)&W[(size_t)o * CN + 2 * pr];
        float4 c0 = coef[2 * pr], c1 = coef[2 * pr + 1];
        float s0, s1, f0, f1;
        if (z == 0)      { s0 = c0.x; f0 = c0.y; s1 = c1.x; f1 = c1.y; }
        else if (z == 3) { s0 = 1.f;  f0 = 0.f;  s1 = 1.f;  f1 = 0.f;  }
        else             { s0 = c0.z; f0 = c0.w; s1 = c1.z; f1 = c1.w; }
        wh[(size_t)z * (CN * CN / 2) + (size_t)o * (CN / 2) + pr] =
            pack_f16(outsc * w2.x * s0, outsc * w2.y * s1);
        part += w2.x * f0 + w2.y * f1;
    }
    #pragma unroll
    for (int off = 16; off >= 1; off >>= 1)
        part += __shfl_xor_sync(0xffffffffu, part, off);
    if (lane == 0) bp[z * CN + o] = outsc * (B[o] + part);
}

// ================= fp16 tensor-core GEMM (R12-verified) =======================
#define GH_W0 0
#define GH_W1 18432
#define GH_X0 36864
#define GH_X1 55296
#define GH_SMEM 73728
#define HPITCH 36     // u32 pitch (144 B)
#define OPITCH 132    // floats, mode-3 transpose staging

__device__ __forceinline__ void gh_load_tiles(
    const uint32_t* __restrict__ Wh, const uint32_t* __restrict__ Xt,
    uint32_t wb, uint32_t xb, int o0, int n0, int kc, int tid)
{
    #pragma unroll
    for (int r = 0; r < 4; r++) {
        int idx = tid + r * 256;
        int row = idx >> 3, g = idx & 7;
        CP_ASYNC16(wb + row * 144 + g * 16,
                   Wh + (size_t)(o0 + row) * (CN / 2) + kc + g * 4);
        CP_ASYNC16(xb + row * 144 + g * 16,
                   Xt + (size_t)(n0 + row) * (CN / 2) + kc + g * 4);
    }
}

__device__ __forceinline__ void gemm_h_body(
    const uint32_t* __restrict__ Wh, const uint32_t* __restrict__ Xt,
    const float* __restrict__ bias, float* __restrict__ Y,
    const float* __restrict__ resid, float oscale, int mode, float scale,
    char* sm, int n0, int o0)
{
    const uint32_t smb = smem_u32(sm);
    const int tid = threadIdx.x, lane = tid & 31, wid = tid >> 5;
    const int wm = wid & 1, wn = wid >> 1;
    const int r0 = lane >> 2, m = lane & 3;

    gh_load_tiles(Wh, Xt, smb + GH_W0, smb + GH_X0, o0, n0, 0, tid);
    CP_COMMIT();

    float acc[4][4][4] = {};

    for (int i = 0; i < 8; i++) {
        if (i < 7) {
            const int kc2 = (i + 1) * 32;
            gh_load_tiles(Wh, Xt,
                          smb + ((i + 1) & 1 ? GH_W1 : GH_W0),
                          smb + ((i + 1) & 1 ? GH_X1 : GH_X0),
                          o0, n0, kc2, tid);
            CP_COMMIT();
            CP_WAIT(1);
        } else {
            CP_WAIT(0);
        }
        __syncthreads();

        const uint32_t* Wb = (const uint32_t*)(sm + ((i & 1) ? GH_W1 : GH_W0));
        const uint32_t* Xb = (const uint32_t*)(sm + ((i & 1) ? GH_X1 : GH_X0));

        #pragma unroll
        for (int kd = 0; kd < 4; kd++) {
            uint32_t aW[4][4];
            #pragma unroll
            for (int mt = 0; mt < 4; mt++) {
                const uint32_t* w0 = Wb + (wm * 64 + mt * 16 + r0) * HPITCH;
                const uint32_t* w8 = w0 + 8 * HPITCH;
                aW[mt][0] = w0[kd * 8 + m];
                aW[mt][1] = w8[kd * 8 + m];
                aW[mt][2] = w0[kd * 8 + 4 + m];
                aW[mt][3] = w8[kd * 8 + 4 + m];
            }
            #pragma unroll
            for (int nt = 0; nt < 4; nt++) {
                const uint32_t* xr = Xb + (wn * 32 + nt * 8 + r0) * HPITCH;
                uint32_t b0 = xr[kd * 8 + m], b1 = xr[kd * 8 + 4 + m];
                #pragma unroll
                for (int mt = 0; mt < 4; mt++)
                    mma_f16(acc[mt][nt], aW[mt], b0, b1);
            }
        }
        __syncthreads();
    }

    if (mode == 0) {
        #pragma unroll
        for (int mt = 0; mt < 4; mt++) {
            int ro = o0 + wm * 64 + mt * 16 + r0;
            float bl = bias[ro], bh = bias[ro + 8];
            #pragma unroll
            for (int nt = 0; nt < 4; nt++) {
                int col = n0 + wn * 32 + nt * 8 + 2 * m;
                size_t a0 = (size_t)ro * NN + col;
                size_t a8 = (size_t)(ro + 8) * NN + col;
                float2 lo = make_float2(acc[mt][nt][0] + bl, acc[mt][nt][1] + bl);
                float2 hi = make_float2(acc[mt][nt][2] + bh, acc[mt][nt][3] + bh);
                if (resid) {
                    float2 rl = *(const float2*)&resid[a0];
                    float2 rh = *(const float2*)&resid[a8];
                    lo.x = (lo.x + rl.x) * oscale; lo.y = (lo.y + rl.y) * oscale;
                    hi.x = (hi.x + rh.x) * oscale; hi.y = (hi.y + rh.y) * oscale;
                }
                *(float2*)&Y[a0] = lo;
                *(float2*)&Y[a8] = hi;
            }
        }
    } else if (mode == 2) {
        uint32_t* Yp = (uint32_t*)Y;
        #pragma unroll
        for (int mt = 0; mt < 4; mt++) {
            int ro = o0 + wm * 64 + mt * 16 + r0;
            float bl = bias[ro], bh = bias[ro + 8];
            #pragma unroll
            for (int nt = 0; nt < 4; nt++) {
                int ch = (n0 >> 1) + wn * 16 + nt * 4 + m;
                Yp[(size_t)ro       * (NN / 2) + ch] =
                    pack_f16(acc[mt][nt][0] + bl, acc[mt][nt][1] + bl);
                Yp[(size_t)(ro + 8) * (NN / 2) + ch] =
                    pack_f16(acc[mt][nt][2] + bh, acc[mt][nt][3] + bh);
            }
        }
    } else {
        float* Os = (float*)sm;
        #pragma unroll
        for (int mt = 0; mt < 4; mt++) {
            int rr = wm * 64 + mt * 16 + r0;
            float bl = bias[o0 + rr], bh = bias[o0 + rr + 8];
            #pragma unroll
            for (int nt = 0; nt < 4; nt++) {
                int cc = wn * 32 + nt * 8 + 2 * m;
                Os[(cc    ) * OPITCH + rr    ] = (acc[mt][nt][0] + bl) * scale;
                Os[(cc + 1) * OPITCH + rr    ] = (acc[mt][nt][1] + bl) * scale;
                Os[(cc    ) * OPITCH + rr + 8] = (acc[mt][nt][2] + bh) * scale;
                Os[(cc + 1) * OPITCH + rr + 8] = (acc[mt][nt][3] + bh) * scale;
            }
        }
        __syncthreads();
        uint32_t* Yh = (uint32_t*)Y;
        #pragma unroll
        for (int r = 0; r < 16; r++) {
            int idx = tid + r * 256;
            int nrow = idx >> 5, j = idx & 31;
            float4 v = *(const float4*)&Os[nrow * OPITCH + j * 4];
            uint2 pk = make_uint2(pack_f16(v.x, v.y), pack_f16(v.z, v.w));
            *(uint2*)&Yh[(size_t)(n0 + nrow) * (CN / 2) + (o0 >> 1) + j * 2] = pk;
        }
    }
}

__global__ __launch_bounds__(256, 1) void gemm_qkv(
    const uint32_t* __restrict__ wh, const float* __restrict__ bp,
    const uint32_t* __restrict__ xt,
    uint32_t* __restrict__ qp, uint32_t* __restrict__ kp, uint32_t* __restrict__ vp)
{
    extern __shared__ char sm[];
    const int n0 = blockIdx.x * 128, o0 = blockIdx.y * 128;
    const int z = blockIdx.z;
    const uint32_t* W = wh + (size_t)z * (CN * CN / 2);
    const float* B = bp + z * CN;
    if (z == 0)
        gemm_h_body(W, xt, B, (float*)qp, nullptr, 1.f, 3, 1.f, sm, n0, o0);
    else if (z == 1)
        gemm_h_body(W, xt, B, (float*)kp, nullptr, 1.f, 3, 1.f, sm, n0, o0);
    else
        gemm_h_body(W, xt, B, (float*)vp, nullptr, 1.f, 2, 1.f, sm, n0, o0);
}

__global__ __launch_bounds__(256, 1) void gemm_out(
    const uint32_t* __restrict__ wh, const float* __restrict__ bp,
    const uint32_t* __restrict__ aot, const float* __restrict__ x,
    float* __restrict__ out)
{
    extern __shared__ char sm[];
    gemm_h_body(wh + (size_t)3 * (CN * CN / 2), aot, bp + 3 * CN, out, x,
                0.70710678118654752f, 0, 1.f, sm, blockIdx.x * 128, blockIdx.y * 128);
}

// ========== fp16 flash attention: ldmatrix + triple-buffer + fma-pipe lsum ====
#define KPITCH  20         // u32 per token row (80 B)
#define KT_SZ   10240
#define VT_SZ   8192
#define AT_KS(b) ((b) * KT_SZ)                  // 0 / 10240 / 20480
#define AT_VS(b) (30720 + (b) * VT_SZ)          // 30720 / 38912 / 47104
#define AT_QS   55296
#define AT_SMEM 65536

__device__ __forceinline__ void load_kv_tile(
    const uint32_t* __restrict__ kp, const uint32_t* __restrict__ vp,
    uint32_t ksdst, uint32_t vsdst, int h, int tile, int tid)
{
    const int m0 = tile * 128;
    #pragma unroll
    for (int r = 0; r < 2; r++) {
        int idx = tid + r * 256;
        int key = idx >> 2, c4 = idx & 3;
        CP_ASYNC16(ksdst + key * 80 + c4 * 16,
                   kp + (size_t)(m0 + key) * (CN / 2) + h * 16 + c4 * 4);
    }
    #pragma unroll
    for (int r = 0; r < 2; r++) {
        int idx = tid + r * 256;
        int c = idx >> 4, t4 = idx & 15;
        CP_ASYNC16(vsdst + t4 * 512 + ((c ^ (t4 & 7)) << 4),
                   vp + (size_t)(h * HD + c) * (NN / 2) + tile * 64 + t4 * 4);
    }
}

__global__ __launch_bounds__(256, 2) void attn_mma(
    const uint32_t* __restrict__ qp, const uint32_t* __restrict__ kp,
    const uint32_t* __restrict__ vp, uint32_t* __restrict__ aot)
{
    extern __shared__ char sm[];
    const uint32_t smb = smem_u32(sm);
    const int tid = threadIdx.x, lane = tid & 31, wid = tid >> 5;
    const int h = blockIdx.y, n0q = blockIdx.x * 128;
    const int r0 = lane >> 2, m = lane & 3;

    // ldmatrix per-lane geometry
    const int Lr = lane & 7, Lm = lane >> 3;
    const uint32_t kofs = (uint32_t)(Lr * 80 + Lm * 16);
    const int tbsel = Lm & 1;
    const int dof0 = ((Lm >> 1) << 3) + Lr;

    // prologue: Q + tile0 (group0), tile1 (group1)
    #pragma unroll
    for (int r = 0; r < 2; r++) {
        int idx = tid + r * 256;
        int row = idx >> 2, c4 = idx & 3;
        CP_ASYNC16(smb + AT_QS + row * 80 + c4 * 16,
                   qp + (size_t)(n0q + row) * (CN / 2) + h * 16 + c4 * 4);
    }
    load_kv_tile(kp, vp, smb + AT_KS(0), smb + AT_VS(0), h, 0, tid);
    CP_COMMIT();
    load_kv_tile(kp, vp, smb + AT_KS(1), smb + AT_VS(1), h, 1, tid);
    CP_COMMIT();
    CP_WAIT(1);
    __syncthreads();

    uint32_t aQ[2][4];
    {
        const uint32_t* Qs = (const uint32_t*)(sm + AT_QS);
        int qr = wid * 16 + r0;
        #pragma unroll
        for (int kk = 0; kk < 2; kk++) {
            aQ[kk][0] = Qs[ qr      * KPITCH + kk * 8 + m];
            aQ[kk][1] = Qs[(qr + 8) * KPITCH + kk * 8 + m];
            aQ[kk][2] = Qs[ qr      * KPITCH + kk * 8 + 4 + m];
            aQ[kk][3] = Qs[(qr + 8) * KPITCH + kk * 8 + 4 + m];
        }
    }

    float O[4][4] = {};
    float ls0 = 0.f, ls1 = 0.f;

    for (int i = 0; i < 32; i++) {
        // ONE barrier per iter: wait tile i, sync, then prefetch into the buffer
        // last read at iter i-1 (all warps provably past it).
        if (i) {
            if (i < 31) CP_WAIT(1); else CP_WAIT(0);
            __syncthreads();
        }
        if (i + 2 < 32) {
            int b = (i + 2) % 3;
            load_kv_tile(kp, vp, smb + AT_KS(b), smb + AT_VS(b), h, i + 2, tid);
            CP_COMMIT();
        }

        const int bi = i % 3;
        const uint32_t ksb = smb + AT_KS(bi) + kofs;
        const uint32_t vsb = smb + AT_VS(bi);

        #pragma unroll
        for (int ks = 0; ks < 8; ks++) {
            uint32_t kb = ksb + ks * 1280;
            uint32_t k0_, k1_, k2_, k3_, k4_, k5_, k6_, k7_;
            ldsm_x4(k0_, k1_, k2_, k3_, kb);
            ldsm_x4(k4_, k5_, k6_, k7_, kb + 640);

            float c0[4] = {}, c1[4] = {};
            mma_f16(c0, aQ[0], k0_, k1_);
            mma_f16(c0, aQ[1], k2_, k3_);
            mma_f16(c1, aQ[0], k4_, k5_);
            mma_f16(c1, aQ[1], k6_, k7_);

            uint32_t apv[4];
            apv[0] = ex2_f16x2(pack_f16(c0[0], c0[1]));
            apv[1] = ex2_f16x2(pack_f16(c0[2], c0[3]));
            apv[2] = ex2_f16x2(pack_f16(c1[0], c1[1]));
            apv[3] = ex2_f16x2(pack_f16(c1[2], c1[3]));

            // lsum on fma pipe (tensor pipe is the binding resource)
            {
                uint32_t hs0 = hadd2(apv[0], apv[2]);   // row r0
                uint32_t hs1 = hadd2(apv[1], apv[3]);   // row r0+8
                float2 f0 = __half22float2(*(__half2*)&hs0);
                float2 f1 = __half22float2(*(__half2*)&hs1);
                ls0 += f0.x + f0.y;
                ls1 += f1.x + f1.y;
            }

            const int tbl = 2 * ks + tbsel;
            const uint32_t vrow = vsb + tbl * 512;
            uint32_t va0 = vrow + (uint32_t)(((dof0     ) ^ (tbl & 7)) << 4);
            uint32_t va1 = vrow + (uint32_t)(((dof0 + 16) ^ (tbl & 7)) << 4);
            uint32_t e0, e1, e2, e3, f0_, f1_, f2_, f3_;
            ldsm_x4(e0, e1, e2, e3, va0);
            ldsm_x4(f0_, f1_, f2_, f3_, va1);

            mma_f16(O[0], apv, e0, e1);
            mma_f16(O[1], apv, e2, e3);
            mma_f16(O[2], apv, f0_, f1_);
            mma_f16(O[3], apv, f2_, f3_);
        }
    }

    // lanes {l, l^1, l^2} share the same q-row
    ls0 += __shfl_xor_sync(0xffffffffu, ls0, 1);
    ls0 += __shfl_xor_sync(0xffffffffu, ls0, 2);
    ls1 += __shfl_xor_sync(0xffffffffu, ls1, 1);
    ls1 += __shfl_xor_sync(0xffffffffu, ls1, 2);
    const float i0 = 1.f / ls0, i1 = 1.f / ls1;

    // normalize + stage to smem (aliases KS0/KS1; disjoint from iter-31 buffers)
    float* Os = (float*)sm;
    const int q0 = wid * 16;
    #pragma unroll
    for (int nt = 0; nt < 4; nt++) {
        Os[(q0 + r0    ) * 33 + nt * 8 + 2 * m    ] = O[nt][0] * i0;
        Os[(q0 + r0    ) * 33 + nt * 8 + 2 * m + 1] = O[nt][1] * i0;
        Os[(q0 + r0 + 8) * 33 + nt * 8 + 2 * m    ] = O[nt][2] * i1;
        Os[(q0 + r0 + 8) * 33 + nt * 8 + 2 * m + 1] = O[nt][3] * i1;
    }
    __syncthreads();
    #pragma unroll
    for (int it = 0; it < 2; it++) {
        int idx = tid + it * 256;
        int tok = idx >> 2, quad = idx & 3;
        const float* os = &Os[tok * 33 + quad * 8];
        uint4 u;
        u.x = pack_f16(os[0], os[1]);
        u.y = pack_f16(os[2], os[3]);
        u.z = pack_f16(os[4], os[5]);
        u.w = pack_f16(os[6], os[7]);
        *(uint4*)&aot[(size_t)(n0q + tok) * (CN / 2) + h * 16 + quad * 4] = u;
    }
}

// ---------------- launch ----------------
extern "C" void kernel_launch(void* const* d_in, const int* in_sizes, int n_in,
                              void* d_out, int out_size)
{
    const float* x  = (const float*)d_in[0];
    const float* gw = (const float*)d_in[1];
    const float* gb = (const float*)d_in[2];
    const float* wq = (const float*)d_in[3];
    const float* bq = (const float*)d_in[4];
    const float* wk = (const float*)d_in[5];
    const float* bk = (const float*)d_in[6];
    const float* wv = (const float*)d_in[7];
    const float* bv = (const float*)d_in[8];
    const float* wo = (const float*)d_in[9];
    const float* bo = (const float*)d_in[10];
    float* out = (float*)d_out;

    uint32_t *xt, *wh, *qpk, *kpk, *vpk, *aot;
    float *bp;
    float2* cst;
    float4* coef;
    cudaGetSymbolAddress((void**)&xt,  g_xt);
    cudaGetSymbolAddress((void**)&wh,  g_wh);
    cudaGetSymbolAddress((void**)&bp,  g_bp);
    cudaGetSymbolAddress((void**)&qpk, g_qp);
    cudaGetSymbolAddress((void**)&kpk, g_kp);
    cudaGetSymbolAddress((void**)&vpk, g_vp);
    cudaGetSymbolAddress((void**)&aot, g_aot);
    cudaGetSymbolAddress((void**)&cst, g_cst);
    cudaGetSymbolAddress((void**)&coef, g_coef);

    cudaFuncSetAttribute(attn_mma, cudaFuncAttributeMaxDynamicSharedMemorySize, AT_SMEM);
    cudaFuncSetAttribute(gemm_qkv, cudaFuncAttributeMaxDynamicSharedMemorySize, GH_SMEM);
    cudaFuncSetAttribute(gemm_out, cudaFuncAttributeMaxDynamicSharedMemorySize, GH_SMEM);

    gn_stats_ch<<<CN, 256>>>(x, cst);
    pack_xt<<<dim3(NN / 128, CN / 16), 256>>>(x, xt);
    gn_coef<<<1, 512>>>(cst, gw, gb, coef);
    pack_w<<<256, 256>>>(wq, wk, wv, wo, bq, bk, bv, bo, coef, wh, bp);

    gemm_qkv<<<dim3(NN / 128, CN / 128, 3), 256, GH_SMEM>>>(wh, bp, xt, qpk, kpk, vpk);

    attn_mma<<<dim3(NN / 128, HEADS), 256, AT_SMEM>>>(qpk, kpk, vpk, aot);

    gemm_out<<<dim3(NN / 128, CN / 128), 256, GH_SMEM>>>(wh, bp, aot, x, out);
}

// round 16
// speedup vs baseline: 1.0521x; 1.0521x over previous
#include <cuda_runtime.h>
#include <cstdint>
#include <math.h>

#define CN 512
#define NN 4096
#define HEADS 16
#define HD 32

// log2(e)/sqrt(32): folded into W'q / b'q so softmax uses ex2
#define QSCALE_LOG2E 0.2550348640f

// ---------------- scratch ----------------
__device__ uint32_t g_xt [NN * (CN / 2)];      // x fp16 c-pair packed, token-major
__device__ uint32_t g_wh [4 * CN * (CN / 2)];  // W' fp16 c-pair packed (q,k,v,o)
__device__ float    g_bp [4 * CN];             // folded biases
__device__ uint32_t g_qp [NN * (CN / 2)];      // Q fp16 d-pair packed, token-major
__device__ uint32_t g_kp [NN * (CN / 2)];      // K fp16 d-pair packed, token-major
__device__ uint32_t g_vp [CN * (NN / 2)];      // V fp16 key-pair packed [c][n/2]
__device__ uint32_t g_aot[NN * (CN / 2)];      // attn out fp16 c-pair packed, token-major
__device__ float2   g_cst[CN];                 // per-channel (sum, sumsq) of x
__device__ float4   g_coef[CN];                // (A1,B1, A21,B21)

// ================= helpers =================
__device__ __forceinline__ uint32_t smem_u32(const void* p){
    uint32_t a;
    asm("{ .reg .u64 t; cvta.to.shared.u64 t, %1; cvt.u32.u64 %0, t; }" : "=r"(a) : "l"(p));
    return a;
}
#define CP_ASYNC16(dst, src) \
    asm volatile("cp.async.cg.shared.global [%0], [%1], 16;" :: "r"(dst), "l"(src) : "memory")
#define CP_COMMIT() asm volatile("cp.async.commit_group;" ::: "memory")
#define CP_WAIT(n)  asm volatile("cp.async.wait_group %0;" :: "n"(n) : "memory")

__device__ __forceinline__ uint32_t pack_f16(float lo, float hi){
    uint32_t d;
    asm("cvt.rn.f16x2.f32 %0, %1, %2;" : "=r"(d) : "f"(hi), "f"(lo));
    return d;
}
__device__ __forceinline__ uint32_t ex2_f16x2(uint32_t x){
    uint32_t y;
    asm("ex2.approx.f16x2 %0, %1;" : "=r"(y) : "r"(x));
    return y;
}
__device__ __forceinline__ void mma_f16(float c[4], const uint32_t a[4], uint32_t b0, uint32_t b1){
    asm volatile("mma.sync.aligned.m16n8k16.row.col.f32.f16.f16.f32 "
        "{%0,%1,%2,%3}, {%4,%5,%6,%7}, {%8,%9}, {%0,%1,%2,%3};"
        : "+f"(c[0]), "+f"(c[1]), "+f"(c[2]), "+f"(c[3])
        : "r"(a[0]), "r"(a[1]), "r"(a[2]), "r"(a[3]), "r"(b0), "r"(b1));
}
__device__ __forceinline__ void ldsm_x4(uint32_t& a, uint32_t& b, uint32_t& c, uint32_t& d,
                                        uint32_t addr){
    asm volatile("ldmatrix.sync.aligned.m8n8.x4.shared.b16 {%0,%1,%2,%3}, [%4];"
        : "=r"(a), "=r"(b), "=r"(c), "=r"(d) : "r"(addr));
}

// ---------------- double-GN coefficients (R10-verified) ----------------
__global__ __launch_bounds__(256) void gn_stats_ch(const float* __restrict__ in,
                                                   float2* __restrict__ cst)
{
    const int c = blockIdx.x;
    const float4* in4 = (const float4*)(in + (size_t)c * NN);
    float s = 0.f, q = 0.f;
    #pragma unroll
    for (int r = 0; r < 4; r++) {
        float4 t = in4[threadIdx.x + r * 256];
        s += t.x + t.y + t.z + t.w;
        q += t.x * t.x + t.y * t.y + t.z * t.z + t.w * t.w;
    }
    __shared__ float rs[8], rq[8];
    #pragma unroll
    for (int o = 16; o >= 1; o >>= 1) {
        s += __shfl_xor_sync(0xffffffffu, s, o);
        q += __shfl_xor_sync(0xffffffffu, q, o);
    }
    int lane = threadIdx.x & 31, wid = threadIdx.x >> 5;
    if (lane == 0) { rs[wid] = s; rq[wid] = q; }
    __syncthreads();
    if (wid == 0) {
        s = (lane < 8) ? rs[lane] : 0.f;
        q = (lane < 8) ? rq[lane] : 0.f;
        #pragma unroll
        for (int o = 4; o >= 1; o >>= 1) {
            s += __shfl_xor_sync(0xffffffffu, s, o);
            q += __shfl_xor_sync(0xffffffffu, q, o);
        }
        if (lane == 0) cst[c] = make_float2(s, q);
    }
}

__global__ __launch_bounds__(512) void gn_coef(
    const float2* __restrict__ cst, const float* __restrict__ w,
    const float* __restrict__ b, float4* __restrict__ coef)
{
    const int c = threadIdx.x;
    float2 p = cst[c];
    float s = p.x, q = p.y;
    #pragma unroll
    for (int o = 8; o >= 1; o >>= 1) {
        s += __shfl_xor_sync(0xffffffffu, s, o);
        q += __shfl_xor_sync(0xffffffffu, q, o);
    }
    const float inv_n = 1.f / 65536.f;
    float m1 = s * inv_n;
    float i1 = rsqrtf(q * inv_n - m1 * m1 + 1e-6f);
    float A1 = w[c] * i1, B1 = b[c] - m1 * A1;
    float mu = p.x * (1.f / 4096.f), e2 = p.y * (1.f / 4096.f);
    float mq = A1 * mu + B1;
    float eq = A1 * A1 * e2 + 2.f * A1 * B1 * mu + B1 * B1;
    float s2 = mq, q2 = eq;
    #pragma unroll
    for (int o = 8; o >= 1; o >>= 1) {
        s2 += __shfl_xor_sync(0xffffffffu, s2, o);
        q2 += __shfl_xor_sync(0xffffffffu, q2, o);
    }
    float m2 = s2 * (1.f / 16.f);
    float i2 = rsqrtf(q2 * (1.f / 16.f) - m2 * m2 + 1e-6f);
    float A2 = w[c] * i2, B2 = b[c] - m2 * A2;
    coef[c] = make_float4(A1, B1, A2 * A1, A2 * B1 + B2);
}

// ---------------- x -> fp16 token-major c-pair packed (staged transpose) -------
__global__ __launch_bounds__(256) void pack_xt(const float* __restrict__ x,
                                               uint32_t* __restrict__ xt)
{
    __shared__ uint32_t ts[8][132];
    const int t = threadIdx.x;
    const int n0 = blockIdx.x * 128, cbase = blockIdx.y * 16;
    const int p = t >> 5, l = t & 31;
    const int c0 = cbase + 2 * p;
    float4 a = *(const float4*)&x[(size_t)c0 * NN + n0 + 4 * l];
    float4 b = *(const float4*)&x[(size_t)(c0 + 1) * NN + n0 + 4 * l];
    uint4 u;
    u.x = pack_f16(a.x, b.x); u.y = pack_f16(a.y, b.y);
    u.z = pack_f16(a.z, b.z); u.w = pack_f16(a.w, b.w);
    *(uint4*)&ts[p][4 * l] = u;
    __syncthreads();
    const int tok = t >> 1, hf = t & 1;
    uint4 v;
    v.x = ts[hf * 4 + 0][tok]; v.y = ts[hf * 4 + 1][tok];
    v.z = ts[hf * 4 + 2][tok]; v.w = ts[hf * 4 + 3][tok];
    *(uint4*)&xt[(size_t)(n0 + tok) * (CN / 2) + (cbase >> 1) + hf * 4] = v;
}

// ---------------- fold GN into weights (R12/R13-verified version) --------------
__global__ __launch_bounds__(256) void pack_w(
    const float* __restrict__ wq_, const float* __restrict__ wk_,
    const float* __restrict__ wv_, const float* __restrict__ wo_,
    const float* __restrict__ bq_, const float* __restrict__ bk_,
    const float* __restrict__ bv_, const float* __restrict__ bo_,
    const float4* __restrict__ coef,
    uint32_t* __restrict__ wh, float* __restrict__ bp)
{
    const int o = blockIdx.x, z = blockIdx.y, t = threadIdx.x;
    const float* W = (z == 0) ? wq_ : (z == 1) ? wk_ : (z == 2) ? wv_ : wo_;
    const float* B = (z == 0) ? bq_ : (z == 1) ? bk_ : (z == 2) ? bv_ : bo_;
    const float outsc = (z == 0) ? QSCALE_LOG2E : 1.f;
    float2 w2 = *(const float2*)&W[(size_t)o * CN + 2 * t];
    float4 c0 = coef[2 * t], c1 = coef[2 * t + 1];
    float s0, s1, f0, f1;
    if (z == 0)      { s0 = c0.x; f0 = c0.y; s1 = c1.x; f1 = c1.y; }
    else if (z == 3) { s0 = 1.f;  f0 = 0.f;  s1 = 1.f;  f1 = 0.f;  }
    else             { s0 = c0.z; f0 = c0.w; s1 = c1.z; f1 = c1.w; }
    wh[(size_t)z * (CN * CN / 2) + (size_t)o * (CN / 2) + t] =
        pack_f16(outsc * w2.x * s0, outsc * w2.y * s1);
    float part = w2.x * f0 + w2.y * f1;
    #pragma unroll
    for (int off = 16; off >= 1; off >>= 1)
        part += __shfl_xor_sync(0xffffffffu, part, off);
    __shared__ float rs[8];
    int lane = t & 31, wid = t >> 5;
    if (lane == 0) rs[wid] = part;
    __syncthreads();
    if (t == 0) {
        float tot = 0.f;
        #pragma unroll
        for (int k = 0; k < 8; k++) tot += rs[k];
        bp[z * CN + o] = outsc * (B[o] + tot);
    }
}

// ================= fp16 tensor-core GEMM with ldmatrix fragment loads =========
#define GH_W0 0
#define GH_W1 18432
#define GH_X0 36864
#define GH_X1 55296
#define GH_SMEM 73728
#define OPITCH 132    // floats, mode-3 transpose staging

__device__ __forceinline__ void gh_load_tiles(
    const uint32_t* __restrict__ Wh, const uint32_t* __restrict__ Xt,
    uint32_t wb, uint32_t xb, int o0, int n0, int kc, int tid)
{
    #pragma unroll
    for (int r = 0; r < 4; r++) {
        int idx = tid + r * 256;
        int row = idx >> 3, g = idx & 7;
        CP_ASYNC16(wb + row * 144 + g * 16,
                   Wh + (size_t)(o0 + row) * (CN / 2) + kc + g * 4);
        CP_ASYNC16(xb + row * 144 + g * 16,
                   Xt + (size_t)(n0 + row) * (CN / 2) + kc + g * 4);
    }
}

__device__ __forceinline__ void gemm_h_body(
    const uint32_t* __restrict__ Wh, const uint32_t* __restrict__ Xt,
    const float* __restrict__ bias, float* __restrict__ Y,
    const float* __restrict__ resid, float oscale, int mode, float scale,
    char* sm, int n0, int o0)
{
    const uint32_t smb = smem_u32(sm);
    const int tid = threadIdx.x, lane = tid & 31, wid = tid >> 5;
    const int wm = wid & 1, wn = wid >> 1;
    const int r0 = lane >> 2, m = lane & 3;
    // ldmatrix lane geometry
    const int Lr = lane & 7, Lm = lane >> 3;
    // A: matrix Lm -> row-oct (Lm&1), k-half (Lm>>1)
    const uint32_t aoff = (uint32_t)((wm * 64 + (Lm & 1) * 8 + Lr) * 144 + (Lm >> 1) * 16);
    // B: matrix Lm -> token-oct (Lm>>1), k-half (Lm&1)
    const uint32_t boff = (uint32_t)((wn * 32 + (Lm >> 1) * 8 + Lr) * 144 + (Lm & 1) * 16);

    gh_load_tiles(Wh, Xt, smb + GH_W0, smb + GH_X0, o0, n0, 0, tid);
    CP_COMMIT();

    float acc[4][4][4] = {};

    for (int i = 0; i < 8; i++) {
        if (i < 7) {
            const int kc2 = (i + 1) * 32;
            gh_load_tiles(Wh, Xt,
                          smb + ((i + 1) & 1 ? GH_W1 : GH_W0),
                          smb + ((i + 1) & 1 ? GH_X1 : GH_X0),
                          o0, n0, kc2, tid);
            CP_COMMIT();
            CP_WAIT(1);
        } else {
            CP_WAIT(0);
        }
        __syncthreads();

        const uint32_t wtb = smb + ((i & 1) ? GH_W1 : GH_W0) + aoff;
        const uint32_t xtb = smb + ((i & 1) ? GH_X1 : GH_X0) + boff;

        #pragma unroll
        for (int kd = 0; kd < 4; kd++) {
            uint32_t aW[4][4];
            #pragma unroll
            for (int mt = 0; mt < 4; mt++)
                ldsm_x4(aW[mt][0], aW[mt][1], aW[mt][2], aW[mt][3],
                        wtb + mt * 2304 + kd * 32);
            uint32_t bX[2][4];
            #pragma unroll
            for (int nt2 = 0; nt2 < 2; nt2++)
                ldsm_x4(bX[nt2][0], bX[nt2][1], bX[nt2][2], bX[nt2][3],
                        xtb + nt2 * 2304 + kd * 32);
            #pragma unroll
            for (int mt = 0; mt < 4; mt++)
                #pragma unroll
                for (int nt = 0; nt < 4; nt++)
                    mma_f16(acc[mt][nt], aW[mt],
                            bX[nt >> 1][(nt & 1) * 2], bX[nt >> 1][(nt & 1) * 2 + 1]);
        }
        __syncthreads();
    }

    // ---------------- epilogues (R10-verified) ----------------
    if (mode == 0) {
        #pragma unroll
        for (int mt = 0; mt < 4; mt++) {
            int ro = o0 + wm * 64 + mt * 16 + r0;
            float bl = bias[ro], bh = bias[ro + 8];
            #pragma unroll
            for (int nt = 0; nt < 4; nt++) {
                int col = n0 + wn * 32 + nt * 8 + 2 * m;
                size_t a0 = (size_t)ro * NN + col;
                size_t a8 = (size_t)(ro + 8) * NN + col;
                float2 lo = make_float2(acc[mt][nt][0] + bl, acc[mt][nt][1] + bl);
                float2 hi = make_float2(acc[mt][nt][2] + bh, acc[mt][nt][3] + bh);
                if (resid) {
                    float2 rl = *(const float2*)&resid[a0];
                    float2 rh = *(const float2*)&resid[a8];
                    lo.x = (lo.x + rl.x) * oscale; lo.y = (lo.y + rl.y) * oscale;
                    hi.x = (hi.x + rh.x) * oscale; hi.y = (hi.y + rh.y) * oscale;
                }
                *(float2*)&Y[a0] = lo;
                *(float2*)&Y[a8] = hi;
            }
        }
    } else if (mode == 2) {
        uint32_t* Yp = (uint32_t*)Y;
        #pragma unroll
        for (int mt = 0; mt < 4; mt++) {
            int ro = o0 + wm * 64 + mt * 16 + r0;
            float bl = bias[ro], bh = bias[ro + 8];
            #pragma unroll
            for (int nt = 0; nt < 4; nt++) {
                int ch = (n0 >> 1) + wn * 16 + nt * 4 + m;
                Yp[(size_t)ro       * (NN / 2) + ch] =
                    pack_f16(acc[mt][nt][0] + bl, acc[mt][nt][1] + bl);
                Yp[(size_t)(ro + 8) * (NN / 2) + ch] =
                    pack_f16(acc[mt][nt][2] + bh, acc[mt][nt][3] + bh);
            }
        }
    } else {
        float* Os = (float*)sm;
        #pragma unroll
        for (int mt = 0; mt < 4; mt++) {
            int rr = wm * 64 + mt * 16 + r0;
            float bl = bias[o0 + rr], bh = bias[o0 + rr + 8];
            #pragma unroll
            for (int nt = 0; nt < 4; nt++) {
                int cc = wn * 32 + nt * 8 + 2 * m;
                Os[(cc    ) * OPITCH + rr    ] = (acc[mt][nt][0] + bl) * scale;
                Os[(cc + 1) * OPITCH + rr    ] = (acc[mt][nt][1] + bl) * scale;
                Os[(cc    ) * OPITCH + rr + 8] = (acc[mt][nt][2] + bh) * scale;
                Os[(cc + 1) * OPITCH + rr + 8] = (acc[mt][nt][3] + bh) * scale;
            }
        }
        __syncthreads();
        uint32_t* Yh = (uint32_t*)Y;
        #pragma unroll
        for (int r = 0; r < 16; r++) {
            int idx = tid + r * 256;
            int nrow = idx >> 5, j = idx & 31;
            float4 v = *(const float4*)&Os[nrow * OPITCH + j * 4];
            uint2 pk = make_uint2(pack_f16(v.x, v.y), pack_f16(v.z, v.w));
            *(uint2*)&Yh[(size_t)(n0 + nrow) * (CN / 2) + (o0 >> 1) + j * 2] = pk;
        }
    }
}

__global__ __launch_bounds__(256, 1) void gemm_qkv(
    const uint32_t* __restrict__ wh, const float* __restrict__ bp,
    const uint32_t* __restrict__ xt,
    uint32_t* __restrict__ qp, uint32_t* __restrict__ kp, uint32_t* __restrict__ vp)
{
    extern __shared__ char sm[];
    const int n0 = blockIdx.x * 128, o0 = blockIdx.y * 128;
    const int z = blockIdx.z;
    const uint32_t* W = wh + (size_t)z * (CN * CN / 2);
    const float* B = bp + z * CN;
    if (z == 0)
        gemm_h_body(W, xt, B, (float*)qp, nullptr, 1.f, 3, 1.f, sm, n0, o0);
    else if (z == 1)
        gemm_h_body(W, xt, B, (float*)kp, nullptr, 1.f, 3, 1.f, sm, n0, o0);
    else
        gemm_h_body(W, xt, B, (float*)vp, nullptr, 1.f, 2, 1.f, sm, n0, o0);
}

__global__ __launch_bounds__(256, 1) void gemm_out(
    const uint32_t* __restrict__ wh, const float* __restrict__ bp,
    const uint32_t* __restrict__ aot, const float* __restrict__ x,
    float* __restrict__ out)
{
    extern __shared__ char sm[];
    gemm_h_body(wh + (size_t)3 * (CN * CN / 2), aot, bp + 3 * CN, out, x,
                0.70710678118654752f, 0, 1.f, sm, blockIdx.x * 128, blockIdx.y * 128);
}

// ========== fp16 flash attention (R13-verified: ldmatrix + ones-mma lsum) =====
#define KPITCH  20         // u32 per token row (80 B)
#define AT_KS0  0
#define AT_KS1  10240
#define AT_VS0  20480
#define AT_VS1  28672
#define AT_QS   36864
#define AT_SMEM 47104
#define ONES_H2 0x3C003C00u

__device__ __forceinline__ void load_kv_tile(
    const uint32_t* __restrict__ kp, const uint32_t* __restrict__ vp,
    uint32_t ksdst, uint32_t vsdst, int h, int tile, int tid)
{
    const int m0 = tile * 128;
    #pragma unroll
    for (int r = 0; r < 2; r++) {
        int idx = tid + r * 256;
        int key = idx >> 2, c4 = idx & 3;
        CP_ASYNC16(ksdst + key * 80 + c4 * 16,
                   kp + (size_t)(m0 + key) * (CN / 2) + h * 16 + c4 * 4);
    }
    #pragma unroll
    for (int r = 0; r < 2; r++) {
        int idx = tid + r * 256;
        int c = idx >> 4, t4 = idx & 15;
        CP_ASYNC16(vsdst + t4 * 512 + ((c ^ (t4 & 7)) << 4),
                   vp + (size_t)(h * HD + c) * (NN / 2) + tile * 64 + t4 * 4);
    }
}

__global__ __launch_bounds__(256, 2) void attn_mma(
    const uint32_t* __restrict__ qp, const uint32_t* __restrict__ kp,
    const uint32_t* __restrict__ vp, uint32_t* __restrict__ aot)
{
    extern __shared__ char sm[];
    const uint32_t smb = smem_u32(sm);
    const int tid = threadIdx.x, lane = tid & 31, wid = tid >> 5;
    const int h = blockIdx.y, n0q = blockIdx.x * 128;
    const int r0 = lane >> 2, m = lane & 3;

    const int Lr = lane & 7, Lm = lane >> 3;
    const uint32_t kofs = (uint32_t)(Lr * 80 + Lm * 16);
    const int tbsel = Lm & 1;
    const int dof0 = ((Lm >> 1) << 3) + Lr;

    #pragma unroll
    for (int r = 0; r < 2; r++) {
        int idx = tid + r * 256;
        int row = idx >> 2, c4 = idx & 3;
        CP_ASYNC16(smb + AT_QS + row * 80 + c4 * 16,
                   qp + (size_t)(n0q + row) * (CN / 2) + h * 16 + c4 * 4);
    }
    load_kv_tile(kp, vp, smb + AT_KS0, smb + AT_VS0, h, 0, tid);
    CP_COMMIT();
    CP_WAIT(0);
    __syncthreads();

    uint32_t aQ[2][4];
    {
        const uint32_t* Qs = (const uint32_t*)(sm + AT_QS);
        int qr = wid * 16 + r0;
        #pragma unroll
        for (int kk = 0; kk < 2; kk++) {
            aQ[kk][0] = Qs[ qr      * KPITCH + kk * 8 + m];
            aQ[kk][1] = Qs[(qr + 8) * KPITCH + kk * 8 + m];
            aQ[kk][2] = Qs[ qr      * KPITCH + kk * 8 + 4 + m];
            aQ[kk][3] = Qs[(qr + 8) * KPITCH + kk * 8 + 4 + m];
        }
    }

    float O[4][4] = {};
    float Lacc[4] = {};

    for (int i = 0; i < 32; i++) {
        if (i < 31) {
            load_kv_tile(kp, vp, smb + ((i + 1) & 1 ? AT_KS1 : AT_KS0),
                                 smb + ((i + 1) & 1 ? AT_VS1 : AT_VS0), h, i + 1, tid);
            CP_COMMIT();
            CP_WAIT(1);
        } else {
            CP_WAIT(0);
        }
        __syncthreads();

        const uint32_t ksb = smb + (i & 1 ? AT_KS1 : AT_KS0) + kofs;
        const uint32_t vsb = smb + (i & 1 ? AT_VS1 : AT_VS0);

        #pragma unroll
        for (int ks = 0; ks < 8; ks++) {
            uint32_t kb = ksb + ks * 1280;
            uint32_t k0_, k1_, k2_, k3_, k4_, k5_, k6_, k7_;
            ldsm_x4(k0_, k1_, k2_, k3_, kb);
            ldsm_x4(k4_, k5_, k6_, k7_, kb + 640);

            float c0[4] = {}, c1[4] = {};
            mma_f16(c0, aQ[0], k0_, k1_);
            mma_f16(c0, aQ[1], k2_, k3_);
            mma_f16(c1, aQ[0], k4_, k5_);
            mma_f16(c1, aQ[1], k6_, k7_);

            uint32_t apv[4];
            apv[0] = ex2_f16x2(pack_f16(c0[0], c0[1]));
            apv[1] = ex2_f16x2(pack_f16(c0[2], c0[3]));
            apv[2] = ex2_f16x2(pack_f16(c1[0], c1[1]));
            apv[3] = ex2_f16x2(pack_f16(c1[2], c1[3]));

            mma_f16(Lacc, apv, ONES_H2, ONES_H2);

            const int tbl = 2 * ks + tbsel;
            const uint32_t vrow = vsb + tbl * 512;
            uint32_t va0 = vrow + (uint32_t)(((dof0     ) ^ (tbl & 7)) << 4);
            uint32_t va1 = vrow + (uint32_t)(((dof0 + 16) ^ (tbl & 7)) << 4);
            uint32_t e0, e1, e2, e3, f0, f1, f2, f3;
            ldsm_x4(e0, e1, e2, e3, va0);
            ldsm_x4(f0, f1, f2, f3, va1);

            mma_f16(O[0], apv, e0, e1);
            mma_f16(O[1], apv, e2, e3);
            mma_f16(O[2], apv, f0, f1);
            mma_f16(O[3], apv, f2, f3);
        }
        __syncthreads();
    }

    const float i0 = 1.f / Lacc[0], i1 = 1.f / Lacc[2];

    float* Os = (float*)sm;
    const int q0 = wid * 16;
    #pragma unroll
    for (int nt = 0; nt < 4; nt++) {
        Os[(q0 + r0    ) * 33 + nt * 8 + 2 * m    ] = O[nt][0] * i0;
        Os[(q0 + r0    ) * 33 + nt * 8 + 2 * m + 1] = O[nt][1] * i0;
        Os[(q0 + r0 + 8) * 33 + nt * 8 + 2 * m    ] = O[nt][2] * i1;
        Os[(q0 + r0 + 8) * 33 + nt * 8 + 2 * m + 1] = O[nt][3] * i1;
    }
    __syncthreads();
    #pragma unroll
    for (int it = 0; it < 2; it++) {
        int idx = tid + it * 256;
        int tok = idx >> 2, quad = idx & 3;
        const float* os = &Os[tok * 33 + quad * 8];
        uint4 u;
        u.x = pack_f16(os[0], os[1]);
        u.y = pack_f16(os[2], os[3]);
        u.z = pack_f16(os[4], os[5]);
        u.w = pack_f16(os[6], os[7]);
        *(uint4*)&aot[(size_t)(n0q + tok) * (CN / 2) + h * 16 + quad * 4] = u;
    }
}

// ---------------- launch ----------------
extern "C" void kernel_launch(void* const* d_in, const int* in_sizes, int n_in,
                              void* d_out, int out_size)
{
    const float* x  = (const float*)d_in[0];
    const float* gw = (const float*)d_in[1];
    const float* gb = (const float*)d_in[2];
    const float* wq = (const float*)d_in[3];
    const float* bq = (const float*)d_in[4];
    const float* wk = (const float*)d_in[5];
    const float* bk = (const float*)d_in[6];
    const float* wv = (const float*)d_in[7];
    const float* bv = (const float*)d_in[8];
    const float* wo = (const float*)d_in[9];
    const float* bo = (const float*)d_in[10];
    float* out = (float*)d_out;

    uint32_t *xt, *wh, *qpk, *kpk, *vpk, *aot;
    float *bp;
    float2* cst;
    float4* coef;
    cudaGetSymbolAddress((void**)&xt,  g_xt);
    cudaGetSymbolAddress((void**)&wh,  g_wh);
    cudaGetSymbolAddress((void**)&bp,  g_bp);
    cudaGetSymbolAddress((void**)&qpk, g_qp);
    cudaGetSymbolAddress((void**)&kpk, g_kp);
    cudaGetSymbolAddress((void**)&vpk, g_vp);
    cudaGetSymbolAddress((void**)&aot, g_aot);
    cudaGetSymbolAddress((void**)&cst, g_cst);
    cudaGetSymbolAddress((void**)&coef, g_coef);

    cudaFuncSetAttribute(attn_mma, cudaFuncAttributeMaxDynamicSharedMemorySize, AT_SMEM);
    cudaFuncSetAttribute(gemm_qkv, cudaFuncAttributeMaxDynamicSharedMemorySize, GH_SMEM);
    cudaFuncSetAttribute(gemm_out, cudaFuncAttributeMaxDynamicSharedMemorySize, GH_SMEM);

    gn_stats_ch<<<CN, 256>>>(x, cst);
    pack_xt<<<dim3(NN / 128, CN / 16), 256>>>(x, xt);
    gn_coef<<<1, 512>>>(cst, gw, gb, coef);
    pack_w<<<dim3(CN, 4), 256>>>(wq, wk, wv, wo, bq, bk, bv, bo, coef, wh, bp);

    gemm_qkv<<<dim3(NN / 128, CN / 128, 3), 256, GH_SMEM>>>(wh, bp, xt, qpk, kpk, vpk);

    attn_mma<<<dim3(NN / 128, HEADS), 256, AT_SMEM>>>(qpk, kpk, vpk, aot);

    gemm_out<<<dim3(NN / 128, CN / 128), 256, GH_SMEM>>>(wh, bp, aot, x, out);
}

// round 17
// speedup vs baseline: 1.0927x; 1.0386x over previous
#include <cuda_runtime.h>
#include <cstdint>
#include <math.h>

#define CN 512
#define NN 4096
#define HEADS 16
#define HD 32

// log2(e)/sqrt(32): folded into W'q / b'q so softmax uses ex2
#define QSCALE_LOG2E 0.2550348640f

// ---------------- scratch ----------------
__device__ uint32_t g_xt [NN * (CN / 2)];      // x fp16 c-pair packed, token-major
__device__ uint32_t g_wh [4 * CN * (CN / 2)];  // W' fp16 c-pair packed (q,k,v,o)
__device__ float    g_bp [4 * CN];             // folded biases
__device__ uint32_t g_qp [NN * (CN / 2)];      // Q fp16 d-pair packed, token-major
__device__ uint32_t g_kp [NN * (CN / 2)];      // K fp16 d-pair packed, token-major
__device__ uint32_t g_vp [CN * (NN / 2)];      // V fp16 key-pair packed [c][n/2]
__device__ uint32_t g_aot[NN * (CN / 2)];      // attn out fp16 c-pair packed, token-major
__device__ float2   g_cst[CN];                 // per-channel (sum, sumsq) of x
__device__ float4   g_coef[CN];                // (A1,B1, A21,B21)

// ================= helpers =================
__device__ __forceinline__ uint32_t smem_u32(const void* p){
    uint32_t a;
    asm("{ .reg .u64 t; cvta.to.shared.u64 t, %1; cvt.u32.u64 %0, t; }" : "=r"(a) : "l"(p));
    return a;
}
#define CP_ASYNC16(dst, src) \
    asm volatile("cp.async.cg.shared.global [%0], [%1], 16;" :: "r"(dst), "l"(src) : "memory")
#define CP_COMMIT() asm volatile("cp.async.commit_group;" ::: "memory")
#define CP_WAIT(n)  asm volatile("cp.async.wait_group %0;" :: "n"(n) : "memory")

__device__ __forceinline__ uint32_t pack_f16(float lo, float hi){
    uint32_t d;
    asm("cvt.rn.f16x2.f32 %0, %1, %2;" : "=r"(d) : "f"(hi), "f"(lo));
    return d;
}
__device__ __forceinline__ uint32_t ex2_f16x2(uint32_t x){
    uint32_t y;
    asm("ex2.approx.f16x2 %0, %1;" : "=r"(y) : "r"(x));
    return y;
}
__device__ __forceinline__ void mma_f16(float c[4], const uint32_t a[4], uint32_t b0, uint32_t b1){
    asm volatile("mma.sync.aligned.m16n8k16.row.col.f32.f16.f16.f32 "
        "{%0,%1,%2,%3}, {%4,%5,%6,%7}, {%8,%9}, {%0,%1,%2,%3};"
        : "+f"(c[0]), "+f"(c[1]), "+f"(c[2]), "+f"(c[3])
        : "r"(a[0]), "r"(a[1]), "r"(a[2]), "r"(a[3]), "r"(b0), "r"(b1));
}
__device__ __forceinline__ void ldsm_x4(uint32_t& a, uint32_t& b, uint32_t& c, uint32_t& d,
                                        uint32_t addr){
    asm volatile("ldmatrix.sync.aligned.m8n8.x4.shared.b16 {%0,%1,%2,%3}, [%4];"
        : "=r"(a), "=r"(b), "=r"(c), "=r"(d) : "r"(addr));
}

// ---------------- double-GN coefficients (R10-verified) ----------------
__global__ __launch_bounds__(256) void gn_stats_ch(const float* __restrict__ in,
                                                   float2* __restrict__ cst)
{
    const int c = blockIdx.x;
    const float4* in4 = (const float4*)(in + (size_t)c * NN);
    float s = 0.f, q = 0.f;
    #pragma unroll
    for (int r = 0; r < 4; r++) {
        float4 t = in4[threadIdx.x + r * 256];
        s += t.x + t.y + t.z + t.w;
        q += t.x * t.x + t.y * t.y + t.z * t.z + t.w * t.w;
    }
    __shared__ float rs[8], rq[8];
    #pragma unroll
    for (int o = 16; o >= 1; o >>= 1) {
        s += __shfl_xor_sync(0xffffffffu, s, o);
        q += __shfl_xor_sync(0xffffffffu, q, o);
    }
    int lane = threadIdx.x & 31, wid = threadIdx.x >> 5;
    if (lane == 0) { rs[wid] = s; rq[wid] = q; }
    __syncthreads();
    if (wid == 0) {
        s = (lane < 8) ? rs[lane] : 0.f;
        q = (lane < 8) ? rq[lane] : 0.f;
        #pragma unroll
        for (int o = 4; o >= 1; o >>= 1) {
            s += __shfl_xor_sync(0xffffffffu, s, o);
            q += __shfl_xor_sync(0xffffffffu, q, o);
        }
        if (lane == 0) cst[c] = make_float2(s, q);
    }
}

__global__ __launch_bounds__(512) void gn_coef(
    const float2* __restrict__ cst, const float* __restrict__ w,
    const float* __restrict__ b, float4* __restrict__ coef)
{
    const int c = threadIdx.x;
    float2 p = cst[c];
    float s = p.x, q = p.y;
    #pragma unroll
    for (int o = 8; o >= 1; o >>= 1) {
        s += __shfl_xor_sync(0xffffffffu, s, o);
        q += __shfl_xor_sync(0xffffffffu, q, o);
    }
    const float inv_n = 1.f / 65536.f;
    float m1 = s * inv_n;
    float i1 = rsqrtf(q * inv_n - m1 * m1 + 1e-6f);
    float A1 = w[c] * i1, B1 = b[c] - m1 * A1;
    float mu = p.x * (1.f / 4096.f), e2 = p.y * (1.f / 4096.f);
    float mq = A1 * mu + B1;
    float eq = A1 * A1 * e2 + 2.f * A1 * B1 * mu + B1 * B1;
    float s2 = mq, q2 = eq;
    #pragma unroll
    for (int o = 8; o >= 1; o >>= 1) {
        s2 += __shfl_xor_sync(0xffffffffu, s2, o);
        q2 += __shfl_xor_sync(0xffffffffu, q2, o);
    }
    float m2 = s2 * (1.f / 16.f);
    float i2 = rsqrtf(q2 * (1.f / 16.f) - m2 * m2 + 1e-6f);
    float A2 = w[c] * i2, B2 = b[c] - m2 * A2;
    coef[c] = make_float4(A1, B1, A2 * A1, A2 * B1 + B2);
}

// ---------------- x -> fp16 token-major c-pair packed (staged transpose) -------
__global__ __launch_bounds__(256) void pack_xt(const float* __restrict__ x,
                                               uint32_t* __restrict__ xt)
{
    __shared__ uint32_t ts[8][132];
    const int t = threadIdx.x;
    const int n0 = blockIdx.x * 128, cbase = blockIdx.y * 16;
    const int p = t >> 5, l = t & 31;
    const int c0 = cbase + 2 * p;
    float4 a = *(const float4*)&x[(size_t)c0 * NN + n0 + 4 * l];
    float4 b = *(const float4*)&x[(size_t)(c0 + 1) * NN + n0 + 4 * l];
    uint4 u;
    u.x = pack_f16(a.x, b.x); u.y = pack_f16(a.y, b.y);
    u.z = pack_f16(a.z, b.z); u.w = pack_f16(a.w, b.w);
    *(uint4*)&ts[p][4 * l] = u;
    __syncthreads();
    const int tok = t >> 1, hf = t & 1;
    uint4 v;
    v.x = ts[hf * 4 + 0][tok]; v.y = ts[hf * 4 + 1][tok];
    v.z = ts[hf * 4 + 2][tok]; v.w = ts[hf * 4 + 3][tok];
    *(uint4*)&xt[(size_t)(n0 + tok) * (CN / 2) + (cbase >> 1) + hf * 4] = v;
}

// ---------------- fold GN into weights (R12/R13-verified version) --------------
__global__ __launch_bounds__(256) void pack_w(
    const float* __restrict__ wq_, const float* __restrict__ wk_,
    const float* __restrict__ wv_, const float* __restrict__ wo_,
    const float* __restrict__ bq_, const float* __restrict__ bk_,
    const float* __restrict__ bv_, const float* __restrict__ bo_,
    const float4* __restrict__ coef,
    uint32_t* __restrict__ wh, float* __restrict__ bp)
{
    const int o = blockIdx.x, z = blockIdx.y, t = threadIdx.x;
    const float* W = (z == 0) ? wq_ : (z == 1) ? wk_ : (z == 2) ? wv_ : wo_;
    const float* B = (z == 0) ? bq_ : (z == 1) ? bk_ : (z == 2) ? bv_ : bo_;
    const float outsc = (z == 0) ? QSCALE_LOG2E : 1.f;
    float2 w2 = *(const float2*)&W[(size_t)o * CN + 2 * t];
    float4 c0 = coef[2 * t], c1 = coef[2 * t + 1];
    float s0, s1, f0, f1;
    if (z == 0)      { s0 = c0.x; f0 = c0.y; s1 = c1.x; f1 = c1.y; }
    else if (z == 3) { s0 = 1.f;  f0 = 0.f;  s1 = 1.f;  f1 = 0.f;  }
    else             { s0 = c0.z; f0 = c0.w; s1 = c1.z; f1 = c1.w; }
    wh[(size_t)z * (CN * CN / 2) + (size_t)o * (CN / 2) + t] =
        pack_f16(outsc * w2.x * s0, outsc * w2.y * s1);
    float part = w2.x * f0 + w2.y * f1;
    #pragma unroll
    for (int off = 16; off >= 1; off >>= 1)
        part += __shfl_xor_sync(0xffffffffu, part, off);
    __shared__ float rs[8];
    int lane = t & 31, wid = t >> 5;
    if (lane == 0) rs[wid] = part;
    __syncthreads();
    if (t == 0) {
        float tot = 0.f;
        #pragma unroll
        for (int k = 0; k < 8; k++) tot += rs[k];
        bp[z * CN + o] = outsc * (B[o] + tot);
    }
}

// ================= fp16 tensor-core GEMM, ldmatrix loads, 2 CTA/SM ============
#define GH_W0 0
#define GH_W1 18432
#define GH_X0 36864
#define GH_X1 55296
#define GH_SMEM 73728
#define OPITCH 132    // floats, mode-3 transpose staging

__device__ __forceinline__ void gh_load_tiles(
    const uint32_t* __restrict__ Wh, const uint32_t* __restrict__ Xt,
    uint32_t wb, uint32_t xb, int o0, int n0, int kc, int tid)
{
    #pragma unroll
    for (int r = 0; r < 4; r++) {
        int idx = tid + r * 256;
        int row = idx >> 3, g = idx & 7;
        CP_ASYNC16(wb + row * 144 + g * 16,
                   Wh + (size_t)(o0 + row) * (CN / 2) + kc + g * 4);
        CP_ASYNC16(xb + row * 144 + g * 16,
                   Xt + (size_t)(n0 + row) * (CN / 2) + kc + g * 4);
    }
}

__device__ __forceinline__ void gemm_h_body(
    const uint32_t* __restrict__ Wh, const uint32_t* __restrict__ Xt,
    const float* __restrict__ bias, float* __restrict__ Y,
    const float* __restrict__ resid, float oscale, int mode, float scale,
    char* sm, int n0, int o0)
{
    const uint32_t smb = smem_u32(sm);
    const int tid = threadIdx.x, lane = tid & 31, wid = tid >> 5;
    const int wm = wid & 1, wn = wid >> 1;
    const int r0 = lane >> 2, m = lane & 3;
    const int Lr = lane & 7, Lm = lane >> 3;
    const uint32_t aoff = (uint32_t)((wm * 64 + (Lm & 1) * 8 + Lr) * 144 + (Lm >> 1) * 16);
    const uint32_t boff = (uint32_t)((wn * 32 + (Lm >> 1) * 8 + Lr) * 144 + (Lm & 1) * 16);

    gh_load_tiles(Wh, Xt, smb + GH_W0, smb + GH_X0, o0, n0, 0, tid);
    CP_COMMIT();

    float acc[4][4][4] = {};

    for (int i = 0; i < 8; i++) {
        if (i < 7) {
            const int kc2 = (i + 1) * 32;
            gh_load_tiles(Wh, Xt,
                          smb + ((i + 1) & 1 ? GH_W1 : GH_W0),
                          smb + ((i + 1) & 1 ? GH_X1 : GH_X0),
                          o0, n0, kc2, tid);
            CP_COMMIT();
            CP_WAIT(1);
        } else {
            CP_WAIT(0);
        }
        __syncthreads();

        const uint32_t wtb = smb + ((i & 1) ? GH_W1 : GH_W0) + aoff;
        const uint32_t xtb = smb + ((i & 1) ? GH_X1 : GH_X0) + boff;

        #pragma unroll
        for (int kd = 0; kd < 4; kd++) {
            uint32_t aW[4][4];
            #pragma unroll
            for (int mt = 0; mt < 4; mt++)
                ldsm_x4(aW[mt][0], aW[mt][1], aW[mt][2], aW[mt][3],
                        wtb + mt * 2304 + kd * 32);
            uint32_t bX[2][4];
            #pragma unroll
            for (int nt2 = 0; nt2 < 2; nt2++)
                ldsm_x4(bX[nt2][0], bX[nt2][1], bX[nt2][2], bX[nt2][3],
                        xtb + nt2 * 2304 + kd * 32);
            #pragma unroll
            for (int mt = 0; mt < 4; mt++)
                #pragma unroll
                for (int nt = 0; nt < 4; nt++)
                    mma_f16(acc[mt][nt], aW[mt],
                            bX[nt >> 1][(nt & 1) * 2], bX[nt >> 1][(nt & 1) * 2 + 1]);
        }
        __syncthreads();
    }

    // ---------------- epilogues (R10-verified) ----------------
    if (mode == 0) {
        #pragma unroll
        for (int mt = 0; mt < 4; mt++) {
            int ro = o0 + wm * 64 + mt * 16 + r0;
            float bl = bias[ro], bh = bias[ro + 8];
            #pragma unroll
            for (int nt = 0; nt < 4; nt++) {
                int col = n0 + wn * 32 + nt * 8 + 2 * m;
                size_t a0 = (size_t)ro * NN + col;
                size_t a8 = (size_t)(ro + 8) * NN + col;
                float2 lo = make_float2(acc[mt][nt][0] + bl, acc[mt][nt][1] + bl);
                float2 hi = make_float2(acc[mt][nt][2] + bh, acc[mt][nt][3] + bh);
                if (resid) {
                    float2 rl = *(const float2*)&resid[a0];
                    float2 rh = *(const float2*)&resid[a8];
                    lo.x = (lo.x + rl.x) * oscale; lo.y = (lo.y + rl.y) * oscale;
                    hi.x = (hi.x + rh.x) * oscale; hi.y = (hi.y + rh.y) * oscale;
                }
                *(float2*)&Y[a0] = lo;
                *(float2*)&Y[a8] = hi;
            }
        }
    } else if (mode == 2) {
        uint32_t* Yp = (uint32_t*)Y;
        #pragma unroll
        for (int mt = 0; mt < 4; mt++) {
            int ro = o0 + wm * 64 + mt * 16 + r0;
            float bl = bias[ro], bh = bias[ro + 8];
            #pragma unroll
            for (int nt = 0; nt < 4; nt++) {
                int ch = (n0 >> 1) + wn * 16 + nt * 4 + m;
                Yp[(size_t)ro       * (NN / 2) + ch] =
                    pack_f16(acc[mt][nt][0] + bl, acc[mt][nt][1] + bl);
                Yp[(size_t)(ro + 8) * (NN / 2) + ch] =
                    pack_f16(acc[mt][nt][2] + bh, acc[mt][nt][3] + bh);
            }
        }
    } else {
        float* Os = (float*)sm;
        #pragma unroll
        for (int mt = 0; mt < 4; mt++) {
            int rr = wm * 64 + mt * 16 + r0;
            float bl = bias[o0 + rr], bh = bias[o0 + rr + 8];
            #pragma unroll
            for (int nt = 0; nt < 4; nt++) {
                int cc = wn * 32 + nt * 8 + 2 * m;
                Os[(cc    ) * OPITCH + rr    ] = (acc[mt][nt][0] + bl) * scale;
                Os[(cc + 1) * OPITCH + rr    ] = (acc[mt][nt][1] + bl) * scale;
                Os[(cc    ) * OPITCH + rr + 8] = (acc[mt][nt][2] + bh) * scale;
                Os[(cc + 1) * OPITCH + rr + 8] = (acc[mt][nt][3] + bh) * scale;
            }
        }
        __syncthreads();
        uint32_t* Yh = (uint32_t*)Y;
        #pragma unroll
        for (int r = 0; r < 16; r++) {
            int idx = tid + r * 256;
            int nrow = idx >> 5, j = idx & 31;
            float4 v = *(const float4*)&Os[nrow * OPITCH + j * 4];
            uint2 pk = make_uint2(pack_f16(v.x, v.y), pack_f16(v.z, v.w));
            *(uint2*)&Yh[(size_t)(n0 + nrow) * (CN / 2) + (o0 >> 1) + j * 2] = pk;
        }
    }
}

__global__ __launch_bounds__(256, 2) void gemm_qkv(
    const uint32_t* __restrict__ wh, const float* __restrict__ bp,
    const uint32_t* __restrict__ xt,
    uint32_t* __restrict__ qp, uint32_t* __restrict__ kp, uint32_t* __restrict__ vp)
{
    extern __shared__ char sm[];
    const int n0 = blockIdx.x * 128, o0 = blockIdx.y * 128;
    const int z = blockIdx.z;
    const uint32_t* W = wh + (size_t)z * (CN * CN / 2);
    const float* B = bp + z * CN;
    if (z == 0)
        gemm_h_body(W, xt, B, (float*)qp, nullptr, 1.f, 3, 1.f, sm, n0, o0);
    else if (z == 1)
        gemm_h_body(W, xt, B, (float*)kp, nullptr, 1.f, 3, 1.f, sm, n0, o0);
    else
        gemm_h_body(W, xt, B, (float*)vp, nullptr, 1.f, 2, 1.f, sm, n0, o0);
}

__global__ __launch_bounds__(256, 2) void gemm_out(
    const uint32_t* __restrict__ wh, const float* __restrict__ bp,
    const uint32_t* __restrict__ aot, const float* __restrict__ x,
    float* __restrict__ out)
{
    extern __shared__ char sm[];
    gemm_h_body(wh + (size_t)3 * (CN * CN / 2), aot, bp + 3 * CN, out, x,
                0.70710678118654752f, 0, 1.f, sm, blockIdx.x * 128, blockIdx.y * 128);
}

// ========== fp16 flash attention (R13-verified core), 3 CTA/SM ================
#define KPITCH  20         // u32 per token row (80 B)
#define AT_KS0  0
#define AT_KS1  10240
#define AT_VS0  20480
#define AT_VS1  28672
#define AT_QS   36864
#define AT_SMEM 47104
#define ONES_H2 0x3C003C00u

__device__ __forceinline__ void load_kv_tile(
    const uint32_t* __restrict__ kp, const uint32_t* __restrict__ vp,
    uint32_t ksdst, uint32_t vsdst, int h, int tile, int tid)
{
    const int m0 = tile * 128;
    #pragma unroll
    for (int r = 0; r < 2; r++) {
        int idx = tid + r * 256;
        int key = idx >> 2, c4 = idx & 3;
        CP_ASYNC16(ksdst + key * 80 + c4 * 16,
                   kp + (size_t)(m0 + key) * (CN / 2) + h * 16 + c4 * 4);
    }
    #pragma unroll
    for (int r = 0; r < 2; r++) {
        int idx = tid + r * 256;
        int c = idx >> 4, t4 = idx & 15;
        CP_ASYNC16(vsdst + t4 * 512 + ((c ^ (t4 & 7)) << 4),
                   vp + (size_t)(h * HD + c) * (NN / 2) + tile * 64 + t4 * 4);
    }
}

__global__ __launch_bounds__(256, 3) void attn_mma(
    const uint32_t* __restrict__ qp, const uint32_t* __restrict__ kp,
    const uint32_t* __restrict__ vp, uint32_t* __restrict__ aot)
{
    extern __shared__ char sm[];
    const uint32_t smb = smem_u32(sm);
    const int tid = threadIdx.x, lane = tid & 31, wid = tid >> 5;
    const int h = blockIdx.y, n0q = blockIdx.x * 128;
    const int r0 = lane >> 2, m = lane & 3;

    const int Lr = lane & 7, Lm = lane >> 3;
    const uint32_t kofs = (uint32_t)(Lr * 80 + Lm * 16);
    const int tbsel = Lm & 1;
    const int dof0 = ((Lm >> 1) << 3) + Lr;

    #pragma unroll
    for (int r = 0; r < 2; r++) {
        int idx = tid + r * 256;
        int row = idx >> 2, c4 = idx & 3;
        CP_ASYNC16(smb + AT_QS + row * 80 + c4 * 16,
                   qp + (size_t)(n0q + row) * (CN / 2) + h * 16 + c4 * 4);
    }
    load_kv_tile(kp, vp, smb + AT_KS0, smb + AT_VS0, h, 0, tid);
    CP_COMMIT();
    CP_WAIT(0);
    __syncthreads();

    uint32_t aQ[2][4];
    {
        const uint32_t* Qs = (const uint32_t*)(sm + AT_QS);
        int qr = wid * 16 + r0;
        #pragma unroll
        for (int kk = 0; kk < 2; kk++) {
            aQ[kk][0] = Qs[ qr      * KPITCH + kk * 8 + m];
            aQ[kk][1] = Qs[(qr + 8) * KPITCH + kk * 8 + m];
            aQ[kk][2] = Qs[ qr      * KPITCH + kk * 8 + 4 + m];
            aQ[kk][3] = Qs[(qr + 8) * KPITCH + kk * 8 + 4 + m];
        }
    }

    float O[4][4] = {};
    float Lacc[4] = {};

    for (int i = 0; i < 32; i++) {
        if (i < 31) {
            load_kv_tile(kp, vp, smb + ((i + 1) & 1 ? AT_KS1 : AT_KS0),
                                 smb + ((i + 1) & 1 ? AT_VS1 : AT_VS0), h, i + 1, tid);
            CP_COMMIT();
            CP_WAIT(1);
        } else {
            CP_WAIT(0);
        }
        __syncthreads();

        const uint32_t ksb = smb + (i & 1 ? AT_KS1 : AT_KS0) + kofs;
        const uint32_t vsb = smb + (i & 1 ? AT_VS1 : AT_VS0);

        #pragma unroll
        for (int ks = 0; ks < 8; ks++) {
            uint32_t kb = ksb + ks * 1280;
            uint32_t k0_, k1_, k2_, k3_, k4_, k5_, k6_, k7_;
            ldsm_x4(k0_, k1_, k2_, k3_, kb);
            ldsm_x4(k4_, k5_, k6_, k7_, kb + 640);

            float c0[4] = {}, c1[4] = {};
            mma_f16(c0, aQ[0], k0_, k1_);
            mma_f16(c0, aQ[1], k2_, k3_);
            mma_f16(c1, aQ[0], k4_, k5_);
            mma_f16(c1, aQ[1], k6_, k7_);

            uint32_t apv[4];
            apv[0] = ex2_f16x2(pack_f16(c0[0], c0[1]));
            apv[1] = ex2_f16x2(pack_f16(c0[2], c0[3]));
            apv[2] = ex2_f16x2(pack_f16(c1[0], c1[1]));
            apv[3] = ex2_f16x2(pack_f16(c1[2], c1[3]));

            mma_f16(Lacc, apv, ONES_H2, ONES_H2);

            const int tbl = 2 * ks + tbsel;
            const uint32_t vrow = vsb + tbl * 512;
            uint32_t va0 = vrow + (uint32_t)(((dof0     ) ^ (tbl & 7)) << 4);
            uint32_t va1 = vrow + (uint32_t)(((dof0 + 16) ^ (tbl & 7)) << 4);
            uint32_t e0, e1, e2, e3, f0, f1, f2, f3;
            ldsm_x4(e0, e1, e2, e3, va0);
            ldsm_x4(f0, f1, f2, f3, va1);

            mma_f16(O[0], apv, e0, e1);
            mma_f16(O[1], apv, e2, e3);
            mma_f16(O[2], apv, f0, f1);
            mma_f16(O[3], apv, f2, f3);
        }
        __syncthreads();
    }

    const float i0 = 1.f / Lacc[0], i1 = 1.f / Lacc[2];

    float* Os = (float*)sm;
    const int q0 = wid * 16;
    #pragma unroll
    for (int nt = 0; nt < 4; nt++) {
        Os[(q0 + r0    ) * 33 + nt * 8 + 2 * m    ] = O[nt][0] * i0;
        Os[(q0 + r0    ) * 33 + nt * 8 + 2 * m + 1] = O[nt][1] * i0;
        Os[(q0 + r0 + 8) * 33 + nt * 8 + 2 * m    ] = O[nt][2] * i1;
        Os[(q0 + r0 + 8) * 33 + nt * 8 + 2 * m + 1] = O[nt][3] * i1;
    }
    __syncthreads();
    #pragma unroll
    for (int it = 0; it < 2; it++) {
        int idx = tid + it * 256;
        int tok = idx >> 2, quad = idx & 3;
        const float* os = &Os[tok * 33 + quad * 8];
        uint4 u;
        u.x = pack_f16(os[0], os[1]);
        u.y = pack_f16(os[2], os[3]);
        u.z = pack_f16(os[4], os[5]);
        u.w = pack_f16(os[6], os[7]);
        *(uint4*)&aot[(size_t)(n0q + tok) * (CN / 2) + h * 16 + quad * 4] = u;
    }
}

// ---------------- launch ----------------
extern "C" void kernel_launch(void* const* d_in, const int* in_sizes, int n_in,
                              void* d_out, int out_size)
{
    const float* x  = (const float*)d_in[0];
    const float* gw = (const float*)d_in[1];
    const float* gb = (const float*)d_in[2];
    const float* wq = (const float*)d_in[3];
    const float* bq = (const float*)d_in[4];
    const float* wk = (const float*)d_in[5];
    const float* bk = (const float*)d_in[6];
    const float* wv = (const float*)d_in[7];
    const float* bv = (const float*)d_in[8];
    const float* wo = (const float*)d_in[9];
    const float* bo = (const float*)d_in[10];
    float* out = (float*)d_out;

    uint32_t *xt, *wh, *qpk, *kpk, *vpk, *aot;
    float *bp;
    float2* cst;
    float4* coef;
    cudaGetSymbolAddress((void**)&xt,  g_xt);
    cudaGetSymbolAddress((void**)&wh,  g_wh);
    cudaGetSymbolAddress((void**)&bp,  g_bp);
    cudaGetSymbolAddress((void**)&qpk, g_qp);
    cudaGetSymbolAddress((void**)&kpk, g_kp);
    cudaGetSymbolAddress((void**)&vpk, g_vp);
    cudaGetSymbolAddress((void**)&aot, g_aot);
    cudaGetSymbolAddress((void**)&cst, g_cst);
    cudaGetSymbolAddress((void**)&coef, g_coef);

    cudaFuncSetAttribute(attn_mma, cudaFuncAttributeMaxDynamicSharedMemorySize, AT_SMEM);
    cudaFuncSetAttribute(gemm_qkv, cudaFuncAttributeMaxDynamicSharedMemorySize, GH_SMEM);
    cudaFuncSetAttribute(gemm_out, cudaFuncAttributeMaxDynamicSharedMemorySize, GH_SMEM);

    gn_stats_ch<<<CN, 256>>>(x, cst);
    pack_xt<<<dim3(NN / 128, CN / 16), 256>>>(x, xt);
    gn_coef<<<1, 512>>>(cst, gw, gb, coef);
    pack_w<<<dim3(CN, 4), 256>>>(wq, wk, wv, wo, bq, bk, bv, bo, coef, wh, bp);

    gemm_qkv<<<dim3(NN / 128, CN / 128, 3), 256, GH_SMEM>>>(wh, bp, xt, qpk, kpk, vpk);

    attn_mma<<<dim3(NN / 128, HEADS), 256, AT_SMEM>>>(qpk, kpk, vpk, aot);

    gemm_out<<<dim3(NN / 128, CN / 128), 256, GH_SMEM>>>(wh, bp, aot, x, out);
}